// round 5
// baseline (speedup 1.0000x reference)
#include <cuda_runtime.h>

typedef unsigned long long u64;

#define KNB   16
#define FIN   7
#define FHID  40
#define FOUT  3
#define TILE  128
#define NODE_STRIDE 116     // floats per node in smem: 112 data + 4 pad = 29 x 16B (odd granule count -> conflict-free LDS.128)
#define NGRP  8
#define HG    5             // hidden units per register group (8*5 = 40)

// ---- packed f32x2 helpers ----
__device__ __forceinline__ u64 pk2(float lo, float hi) {
    u64 r; asm("mov.b64 %0, {%1,%2};" : "=l"(r) : "f"(lo), "f"(hi)); return r;
}
__device__ __forceinline__ void upk2(u64 v, float& lo, float& hi) {
    asm("mov.b64 {%0,%1}, %2;" : "=f"(lo), "=f"(hi) : "l"(v));
}
__device__ __forceinline__ u64 ffma2(u64 a, u64 b, u64 c) {
    u64 d; asm("fma.rn.f32x2 %0, %1, %2, %3;" : "=l"(d) : "l"(a), "l"(b), "l"(c)); return d;
}
__device__ __forceinline__ u64 fadd2(u64 a, u64 b) {
    u64 d; asm("add.rn.f32x2 %0, %1, %2;" : "=l"(d) : "l"(a), "l"(b)); return d;
}

// smem: s_x[TILE][116] floats (transposed per node: [f][k], k contiguous)
//       s_w1d[40][8] u64: [h][f]=dup(W1[f][h]) for f<7, [h][7]=dup(b1[h])
//       s_w2d[40][3] u64: dup(W2[h][o])
//       s_b2[4] float
#define SMEM_X_FLOATS (TILE * NODE_STRIDE)
#define SMEM_BYTES    (SMEM_X_FLOATS * 4 + FHID * 8 * 8 + FHID * FOUT * 8 + 16)

__global__ __launch_bounds__(128, 3)
void aggre_kernel(const float* __restrict__ mailbox,
                  const float* __restrict__ W1,
                  const float* __restrict__ b1,
                  const float* __restrict__ W2,
                  const float* __restrict__ b2,
                  float* __restrict__ out,
                  int n_nodes)
{
    extern __shared__ __align__(16) float4 smem4[];
    float* s_x  = reinterpret_cast<float*>(smem4);
    u64*   s_w1 = reinterpret_cast<u64*>(s_x + SMEM_X_FLOATS);   // [40*8]
    u64*   s_w2 = s_w1 + FHID * 8;                               // [40*3]
    float* s_b2 = reinterpret_cast<float*>(s_w2 + FHID * FOUT);

    const int tid   = threadIdx.x;
    const int nbase = blockIdx.x * TILE;
    const int nval  = min(TILE, n_nodes - nbase);

    // ---- stage weights, lane-duplicated (tiny, one-time) ----
    for (int i = tid; i < FHID * 8; i += 128) {
        int h = i >> 3, f = i & 7;
        float v = (f < FIN) ? W1[f * FHID + h] : b1[h];
        s_w1[i] = pk2(v, v);
    }
    for (int i = tid; i < FHID * FOUT; i += 128) {
        float v = W2[i];                 // W2 row-major [h][o] -> index h*3+o = i
        s_w2[i] = pk2(v, v);
    }
    if (tid < FOUT) s_b2[tid] = b2[tid];

    // ---- stage mailbox tile TRANSPOSED: s_x[n][f*16 + k] = x[n][k][f] ----
    // tile = 128 nodes x 112 floats. 7*128 = 8*112, so for fixed j (0..6) and
    // thread tid, g = j*128 + tid + m*896 has constant (k, f) and node += 8*m.
    {
        const float* src = mailbox + (size_t)nbase * (KNB * FIN);
        if (nval == TILE) {
            #pragma unroll
            for (int j = 0; j < 7; j++) {
                int g0 = j * 128 + tid;
                int n = g0 / 112;
                int r = g0 - n * 112;
                int k = r / 7;
                int f = r - k * 7;
                const float* gp = src + g0;
                float* sp = s_x + n * NODE_STRIDE + f * 16 + k;
                #pragma unroll
                for (int m = 0; m < 16; m++)
                    sp[m * 8 * NODE_STRIDE] = gp[m * 896];
            }
        } else {
            int total = nval * (KNB * FIN);
            for (int it = 0; it < 112; it++) {
                int g = it * 128 + tid;
                if (g < total) {
                    int n = g / 112;
                    int r = g - n * 112;
                    int k = r / 7;
                    int f = r - k * 7;
                    s_x[n * NODE_STRIDE + f * 16 + k] = src[g];
                }
            }
        }
    }
    __syncthreads();

    // ---- per-node compute: f32x2 lanes = (message 2j, message 2j+1) ----
    if (nbase + tid < n_nodes) {
        const float* xrow = s_x + tid * NODE_STRIDE;

        u64 y[FOUT] = {0ULL, 0ULL, 0ULL};   // lanes = (sum over even msgs, odd msgs)

        #pragma unroll 1
        for (int gg = 0; gg < NGRP; gg++) {
            // weights for this group's HG hidden units (lane-duplicated)
            u64 w[HG][FIN], bp[HG];
            #pragma unroll
            for (int h = 0; h < HG; h++) {
                const ulonglong2* row =
                    reinterpret_cast<const ulonglong2*>(s_w1 + (gg * HG + h) * 8);
                ulonglong2 p0 = row[0], p1 = row[1], p2 = row[2], p3 = row[3];
                w[h][0] = p0.x; w[h][1] = p0.y; w[h][2] = p1.x; w[h][3] = p1.y;
                w[h][4] = p2.x; w[h][5] = p2.y; w[h][6] = p3.x; bp[h] = p3.y;
            }

            u64 hs[HG] = {0ULL, 0ULL, 0ULL, 0ULL, 0ULL};

            #pragma unroll
            for (int jpc = 0; jpc < 4; jpc++) {      // 4 chunks of 4 messages
                // one LDS.128 per feature: .x = msgs (4jpc, 4jpc+1), .y = (4jpc+2, 4jpc+3)
                ulonglong2 lv[FIN];
                #pragma unroll
                for (int f = 0; f < FIN; f++)
                    lv[f] = *reinterpret_cast<const ulonglong2*>(xrow + f * 16 + jpc * 4);

                #pragma unroll
                for (int h = 0; h < HG; h++) {
                    u64 aA = bp[h], aB = bp[h];
                    #pragma unroll
                    for (int f = 0; f < FIN; f++) {
                        aA = ffma2(lv[f].x, w[h][f], aA);
                        aB = ffma2(lv[f].y, w[h][f], aB);
                    }
                    float a0, a1, c0, c1;
                    upk2(aA, a0, a1);
                    upk2(aB, c0, c1);
                    hs[h] = fadd2(hs[h], pk2(fmaxf(a0, 0.f), fmaxf(a1, 0.f)));
                    hs[h] = fadd2(hs[h], pk2(fmaxf(c0, 0.f), fmaxf(c1, 0.f)));
                }
            }

            // fold this group's hidden sums into packed outputs
            #pragma unroll
            for (int h = 0; h < HG; h++) {
                int hh = gg * HG + h;
                #pragma unroll
                for (int o = 0; o < FOUT; o++)
                    y[o] = ffma2(hs[h], s_w2[hh * FOUT + o], y[o]);
            }
        }

        const float inv = 1.0f / 16.0f;
        float* op = out + (size_t)(nbase + tid) * FOUT;
        #pragma unroll
        for (int o = 0; o < FOUT; o++) {
            float lo, hi; upk2(y[o], lo, hi);
            op[o] = fmaf(lo + hi, inv, s_b2[o]);
        }
    }
}

extern "C" void kernel_launch(void* const* d_in, const int* in_sizes, int n_in,
                              void* d_out, int out_size)
{
    const float* mailbox = (const float*)d_in[0];
    const float* W1      = (const float*)d_in[1];
    const float* b1      = (const float*)d_in[2];
    const float* W2      = (const float*)d_in[3];
    const float* b2      = (const float*)d_in[4];
    float* out = (float*)d_out;

    int n_nodes = in_sizes[0] / (KNB * FIN);
    int blocks  = (n_nodes + TILE - 1) / TILE;

    static bool attr_set = false;
    if (!attr_set) {
        cudaFuncSetAttribute(aggre_kernel,
                             cudaFuncAttributeMaxDynamicSharedMemorySize, SMEM_BYTES);
        attr_set = true;
    }
    aggre_kernel<<<blocks, 128, SMEM_BYTES>>>(mailbox, W1, b1, W2, b2, out, n_nodes);
}